// round 15
// baseline (speedup 1.0000x reference)
#include <cuda_runtime.h>
#include <math.h>

#define HH 256
#define WW 256
#define HD 512

// ---------------- scratch (device globals) ----------------
__device__ float g_S[2 * 4096];                      // xd^T xd per batch
__device__ float g_M[2 * 4096];                      // Wv @ A^T @ Wproj per batch
__device__ float g_Wp[4096];                         // Wv @ Wc1d
__device__ float g_P[(size_t)2 * HH * WW * 64];      // p_pre

// 4x4 outer-product micro-op: acc[s] += sum_k a.k * bk.s
__device__ __forceinline__ void mk44(float4 a, float4 b0, float4 b1, float4 b2, float4 b3,
                                     float* acc) {
    acc[0] += a.x * b0.x + a.y * b1.x + a.z * b2.x + a.w * b3.x;
    acc[1] += a.x * b0.y + a.y * b1.y + a.z * b2.y + a.w * b3.y;
    acc[2] += a.x * b0.z + a.y * b1.z + a.z * b2.z + a.w * b3.z;
    acc[3] += a.x * b0.w + a.y * b1.w + a.z * b2.w + a.w * b3.w;
}

// ---------------- K0: zero accumulators (g_S, g_M) ----------------
__global__ void k0_zero() {
    int i = blockIdx.x * 1024 + threadIdx.x;
    if (i < 8192) { g_S[i] = 0.f; g_M[i] = 0.f; }
}

// ---------------- KWp: Wp = Wv @ Wc1d, direct per-element (grid 16 x 256) ----------------
__global__ void kWp(const float* __restrict__ Wv, const float* __restrict__ Wc1d) {
    int tid = threadIdx.x;
    int c = blockIdx.x * 4 + (tid >> 6);
    int d = tid & 63;
    const float* wv = Wv + (size_t)c * HD;
    float a = 0.f;
#pragma unroll 8
    for (int f = 0; f < HD; f++)
        a += wv[f] * __ldg(&Wc1d[f * 64 + d]);
    g_Wp[c * 64 + d] = a;
}

// ---------------- K1: S partials (grid 128) ----------------
__global__ void k1_S(const float* __restrict__ x) {
    __shared__ float xs[16 * 64];
    int blk = blockIdx.x, tid = threadIdx.x;
    int b = blk >> 6, rp = blk & 63;      // 2 ds-rows per block
    int ti = tid >> 4, tj = tid & 15;
    int c4 = (tid & 15) * 4;
    int tl = tid >> 4;
    float acc[4][4];
#pragma unroll
    for (int r = 0; r < 4; r++)
#pragma unroll
        for (int s = 0; s < 4; s++) acc[r][s] = 0.f;

    for (int g = 0; g < 16; g++) {
        int dr = rp * 2 + (g >> 3);
        int dc = (g & 7) * 16 + tl;
        int gy = dr * 2, gx = dc * 2;
        const float* p0 = x + (((size_t)b * HH + gy) * WW + gx) * 64 + c4;
        float4 v0 = *(const float4*)p0;
        float4 v1 = *(const float4*)(p0 + 64);
        float4 v2 = *(const float4*)(p0 + WW * 64);
        float4 v3 = *(const float4*)(p0 + WW * 64 + 64);
        float4 s4;
        s4.x = 0.25f * (v0.x + v1.x + v2.x + v3.x);
        s4.y = 0.25f * (v0.y + v1.y + v2.y + v3.y);
        s4.z = 0.25f * (v0.z + v1.z + v2.z + v3.z);
        s4.w = 0.25f * (v0.w + v1.w + v2.w + v3.w);
        *(float4*)&xs[tl * 64 + c4] = s4;
        __syncthreads();
#pragma unroll
        for (int t = 0; t < 16; t++) {
            float4 av = *(const float4*)&xs[t * 64 + 4 * ti];
            float4 bv = *(const float4*)&xs[t * 64 + 4 * tj];
            float a4[4] = {av.x, av.y, av.z, av.w};
            float b4[4] = {bv.x, bv.y, bv.z, bv.w};
#pragma unroll
            for (int r = 0; r < 4; r++)
#pragma unroll
                for (int s = 0; s < 4; s++) acc[r][s] += a4[r] * b4[s];
        }
        __syncthreads();
    }
    float* Sb = g_S + b * 4096;
#pragma unroll
    for (int r = 0; r < 4; r++)
#pragma unroll
        for (int s = 0; s < 4; s++)
            atomicAdd(&Sb[(4 * ti + r) * 64 + 4 * tj + s], acc[r][s]);
}

// ---------------- K23: merged S->SQ/SK/norms -> attn -> M  (grid 16, 512 thr) ----------------
__device__ __forceinline__ void gemm_nn(const float* A, const float* B, int row0, int c0,
                                        float acc[2][4]) {
#pragma unroll
    for (int cc4 = 0; cc4 < 64; cc4 += 4) {
        float4 b0 = *(const float4*)&B[(cc4 + 0) * 64 + c0];
        float4 b1 = *(const float4*)&B[(cc4 + 1) * 64 + c0];
        float4 b2 = *(const float4*)&B[(cc4 + 2) * 64 + c0];
        float4 b3 = *(const float4*)&B[(cc4 + 3) * 64 + c0];
        float4 a0 = *(const float4*)&A[row0 * 64 + cc4];
        float4 a1 = *(const float4*)&A[(row0 + 1) * 64 + cc4];
        mk44(a0, b0, b1, b2, b3, acc[0]);
        mk44(a1, b0, b1, b2, b3, acc[1]);
    }
}

__device__ __forceinline__ void gemm_tn(const float* A, const float* B, int row0, int c0,
                                        float acc[2][4]) {
#pragma unroll 8
    for (int cc = 0; cc < 64; cc++) {
        float4 bv = *(const float4*)&B[cc * 64 + c0];
        float a0 = A[cc * 64 + row0];
        float a1 = A[cc * 64 + row0 + 1];
        acc[0][0] += a0 * bv.x; acc[0][1] += a0 * bv.y;
        acc[0][2] += a0 * bv.z; acc[0][3] += a0 * bv.w;
        acc[1][0] += a1 * bv.x; acc[1][1] += a1 * bv.y;
        acc[1][2] += a1 * bv.z; acc[1][3] += a1 * bv.w;
    }
}

__global__ void k23_attn(const float* __restrict__ Wq, const float* __restrict__ Wk,
                         const float* __restrict__ rescale, const float* __restrict__ Wproj,
                         const float* __restrict__ Wv) {
    extern __shared__ float sm[];
    float* sA = sm;
    float* sB = sm + 4096;
    float* sC = sm + 8192;
    float* sD = sm + 12288;
    float* n2 = sm + 16384;
    float* nrm = sm + 16512;
    int blk = blockIdx.x, b = blk >> 3, h = blk & 7;
    int tid = threadIdx.x;
    int row0 = (tid >> 4) * 2;
    int c0 = (tid & 15) * 4;

    for (int u = tid; u < 4096; u += 512) {
        int cc = u >> 6, j = u & 63;
        sA[u] = g_S[b * 4096 + u];
        sB[u] = Wq[cc * HD + h * 64 + j];
        sC[u] = Wk[cc * HD + h * 64 + j];
    }
    if (tid < 128) n2[tid] = 0.f;
    __syncthreads();
    float resc = rescale[h];

    float acc1[2][4];
#pragma unroll
    for (int r = 0; r < 2; r++)
#pragma unroll
        for (int s = 0; s < 4; s++) acc1[r][s] = 0.f;
    gemm_nn(sA, sB, row0, c0, acc1);
#pragma unroll
    for (int r = 0; r < 2; r++)
        *(float4*)&sD[(row0 + r) * 64 + c0] =
            make_float4(acc1[r][0], acc1[r][1], acc1[r][2], acc1[r][3]);
    __syncthreads();

    {
        int j = tid & 63, cp = tid >> 6;
        float p = 0.f;
#pragma unroll
        for (int k = 0; k < 8; k++) {
            int c = cp * 8 + k;
            p += sB[c * 64 + j] * sD[c * 64 + j];
        }
        atomicAdd(&n2[j], p);
    }
    float acc2[2][4];
#pragma unroll
    for (int r = 0; r < 2; r++)
#pragma unroll
        for (int s = 0; s < 4; s++) acc2[r][s] = 0.f;
    gemm_nn(sA, sC, row0, c0, acc2);
    __syncthreads();
#pragma unroll
    for (int r = 0; r < 2; r++)
        *(float4*)&sB[(row0 + r) * 64 + c0] =
            make_float4(acc2[r][0], acc2[r][1], acc2[r][2], acc2[r][3]);   // sB = SK
    __syncthreads();

    {
        int i = tid & 63, cp = tid >> 6;
        float p = 0.f;
#pragma unroll
        for (int k = 0; k < 8; k++) {
            int c = cp * 8 + k;
            p += sC[c * 64 + i] * sB[c * 64 + i];
        }
        atomicAdd(&n2[64 + i], p);
    }
    __syncthreads();
    if (tid < 128) nrm[tid] = fmaxf(sqrtf(fmaxf(n2[tid], 0.f)), 1e-12f);

    float acc3[2][4];
#pragma unroll
    for (int r = 0; r < 2; r++)
#pragma unroll
        for (int s = 0; s < 4; s++) acc3[r][s] = 0.f;
    gemm_tn(sC, sD, row0, c0, acc3);
    for (int u = tid; u < 4096; u += 512) sB[u] = Wproj[h * 4096 + u];
    __syncthreads();
#pragma unroll
    for (int r = 0; r < 2; r++) {
        float ri = resc / nrm[64 + row0 + r];
#pragma unroll
        for (int s = 0; s < 4; s++)
            sA[(row0 + r) * 64 + c0 + s] = acc3[r][s] * ri / nrm[c0 + s];
    }
    __syncthreads();

    {
        int row = tid >> 3, g = tid & 7;
        float4 v0 = *(const float4*)&sA[row * 64 + g * 8];
        float4 v1 = *(const float4*)&sA[row * 64 + g * 8 + 4];
        float m = fmaxf(fmaxf(fmaxf(v0.x, v0.y), fmaxf(v0.z, v0.w)),
                        fmaxf(fmaxf(v1.x, v1.y), fmaxf(v1.z, v1.w)));
#pragma unroll
        for (int k = 1; k < 8; k <<= 1) m = fmaxf(m, __shfl_xor_sync(0xffffffffu, m, k, 8));
        v0.x = expf(v0.x - m); v0.y = expf(v0.y - m); v0.z = expf(v0.z - m); v0.w = expf(v0.w - m);
        v1.x = expf(v1.x - m); v1.y = expf(v1.y - m); v1.z = expf(v1.z - m); v1.w = expf(v1.w - m);
        float ssum = v0.x + v0.y + v0.z + v0.w + v1.x + v1.y + v1.z + v1.w;
#pragma unroll
        for (int k = 1; k < 8; k <<= 1) ssum += __shfl_xor_sync(0xffffffffu, ssum, k, 8);
        float inv = 1.f / ssum;
        v0.x *= inv; v0.y *= inv; v0.z *= inv; v0.w *= inv;
        v1.x *= inv; v1.y *= inv; v1.z *= inv; v1.w *= inv;
        *(float4*)&sA[row * 64 + g * 8] = v0;
        *(float4*)&sA[row * 64 + g * 8 + 4] = v1;
    }
    __syncthreads();

    float acc4[2][4];
#pragma unroll
    for (int r = 0; r < 2; r++)
#pragma unroll
        for (int s = 0; s < 4; s++) acc4[r][s] = 0.f;
    gemm_tn(sA, sB, row0, c0, acc4);
#pragma unroll
    for (int r = 0; r < 2; r++)
        *(float4*)&sD[(row0 + r) * 64 + c0] =
            make_float4(acc4[r][0], acc4[r][1], acc4[r][2], acc4[r][3]);
    for (int u = tid; u < 4096; u += 512) sC[u] = Wv[(u >> 6) * HD + h * 64 + (u & 63)];
    __syncthreads();

    float acc5[2][4];
#pragma unroll
    for (int r = 0; r < 2; r++)
#pragma unroll
        for (int s = 0; s < 4; s++) acc5[r][s] = 0.f;
    gemm_nn(sC, sD, row0, c0, acc5);
#pragma unroll
    for (int r = 0; r < 2; r++)
#pragma unroll
        for (int s = 0; s < 4; s++)
            atomicAdd(&g_M[b * 4096 + (row0 + r) * 64 + c0 + s], acc5[r][s]);
}

// ---------------- K4a2: dual GEMM — g_P = x@Wp + bc1d, out = x@M_b + bproj ----------------
// grid 2048 (64 px/block), 256 thr, 4px x 4ch per thread, two accumulator sets
#define XSP2 68
__global__ void __launch_bounds__(256) k4a2(const float* __restrict__ x,
                                            const float* __restrict__ bc1d,
                                            const float* __restrict__ bproj,
                                            float* __restrict__ out) {
    extern __shared__ float sm[];
    float* Wps = sm;            // 4096
    float* Ms  = sm + 4096;     // 4096
    float* xs  = sm + 8192;     // 64*68 = 4352
    float* bc  = sm + 12544;    // 64
    float* bp  = sm + 12608;    // 64
    int tid = threadIdx.x;
    int blk = blockIdx.x;
    int b = blk >> 10;
    size_t base = (size_t)blk * 4096;
    const float4* src = (const float4*)(x + base);
    for (int u = tid; u < 1024; u += 256) {
        int p = u >> 4, c4 = (u & 15) * 4;
        *(float4*)&xs[p * XSP2 + c4] = src[u];
    }
    for (int u = tid; u < 1024; u += 256) {
        ((float4*)Wps)[u] = ((const float4*)g_Wp)[u];
        ((float4*)Ms)[u]  = ((const float4*)(g_M + b * 4096))[u];
    }
    if (tid < 64) { bc[tid] = bc1d[tid]; bp[tid] = bproj[tid]; }
    __syncthreads();

    int ti = tid >> 4, tj = tid & 15;
    float accP[4][4], accO[4][4];
#pragma unroll
    for (int r = 0; r < 4; r++)
#pragma unroll
        for (int s = 0; s < 4; s++) { accP[r][s] = 0.f; accO[r][s] = 0.f; }
#pragma unroll
    for (int cc4 = 0; cc4 < 64; cc4 += 4) {
        float4 a[4];
#pragma unroll
        for (int r = 0; r < 4; r++)
            a[r] = *(const float4*)&xs[(4 * ti + r) * XSP2 + cc4];
        {
            float4 b0 = *(const float4*)&Wps[(cc4 + 0) * 64 + 4 * tj];
            float4 b1 = *(const float4*)&Wps[(cc4 + 1) * 64 + 4 * tj];
            float4 b2 = *(const float4*)&Wps[(cc4 + 2) * 64 + 4 * tj];
            float4 b3 = *(const float4*)&Wps[(cc4 + 3) * 64 + 4 * tj];
#pragma unroll
            for (int r = 0; r < 4; r++) mk44(a[r], b0, b1, b2, b3, accP[r]);
        }
        {
            float4 b0 = *(const float4*)&Ms[(cc4 + 0) * 64 + 4 * tj];
            float4 b1 = *(const float4*)&Ms[(cc4 + 1) * 64 + 4 * tj];
            float4 b2 = *(const float4*)&Ms[(cc4 + 2) * 64 + 4 * tj];
            float4 b3 = *(const float4*)&Ms[(cc4 + 3) * 64 + 4 * tj];
#pragma unroll
            for (int r = 0; r < 4; r++) mk44(a[r], b0, b1, b2, b3, accO[r]);
        }
    }
    float4 bcv = *(const float4*)&bc[4 * tj];
    float4 bpv = *(const float4*)&bp[4 * tj];
#pragma unroll
    for (int r = 0; r < 4; r++) {
        size_t off = base + (size_t)(4 * ti + r) * 64 + 4 * tj;
        *(float4*)&g_P[off] = make_float4(accP[r][0] + bcv.x, accP[r][1] + bcv.y,
                                          accP[r][2] + bcv.z, accP[r][3] + bcv.w);
        *(float4*)&out[off] = make_float4(accO[r][0] + bpv.x, accO[r][1] + bpv.y,
                                          accO[r][2] + bpv.z, accO[r][3] + bpv.w);
    }
}

// ---------------- K4b2: conv1+GELU+conv2, out += conv (grid 2048, 256 thr) ----------------
__device__ __forceinline__ float gelu_f(float a) {
    return 0.5f * a * (1.f + erff(a * 0.70710678118654752f));
}

__global__ void k4b2(const float* __restrict__ Wpe1, const float* __restrict__ Wpe2,
                     float* __restrict__ out) {
    extern __shared__ float sm4[];
    float* ps  = sm4;            // 12x12x64 = 9216
    float* p1  = sm4 + 9216;     // 10x10x64 = 6400
    float* w1t = sm4 + 15616;    // 576  (transposed: [k][c])
    float* w2s = sm4 + 16192;    // 576  (original:   [c][k])
    int blk = blockIdx.x;
    int b = blk >> 10;
    int rem = blk & 1023;
    int y0 = (rem >> 5) * 8, x0 = (rem & 31) * 8;
    int tid = threadIdx.x;

    for (int u = tid; u < 576; u += 256) {
        int c = u / 9, k = u - c * 9;
        w1t[k * 64 + c] = Wpe1[u];
        w2s[u] = Wpe2[u];
    }
    for (int u = tid; u < 2304; u += 256) {   // halo p_pre (float4)
        int pidx = u >> 4, cgh = (u & 15) * 4;
        int py = pidx / 12, pxx = pidx - py * 12;
        int gy = y0 - 2 + py, gx = x0 - 2 + pxx;
        float4 v = make_float4(0.f, 0.f, 0.f, 0.f);
        if ((unsigned)gy < HH && (unsigned)gx < WW)
            v = *(const float4*)&g_P[(((size_t)(b * HH + gy)) * WW + gx) * 64 + cgh];
        *(float4*)&ps[pidx * 64 + cgh] = v;
    }
    __syncthreads();

    // conv1 + GELU: fixed channel group per thread -> weights hoisted to regs
    {
        int cgc = (tid & 15) * 4;
        float4 wv1[9];
#pragma unroll
        for (int k = 0; k < 9; k++) wv1[k] = *(const float4*)&w1t[k * 64 + cgc];
        for (int u = tid; u < 1600; u += 256) {
            int pidx = u >> 4;
            int py = pidx / 10, pxx = pidx - py * 10;
            int gy = y0 - 1 + py, gx = x0 - 1 + pxx;
            float4 a = make_float4(0.f, 0.f, 0.f, 0.f);
            if ((unsigned)gy < HH && (unsigned)gx < WW) {
#pragma unroll
                for (int ky = 0; ky < 3; ky++)
#pragma unroll
                    for (int kx = 0; kx < 3; kx++) {
                        int k = ky * 3 + kx;
                        float4 pv = *(const float4*)&ps[((py + ky) * 12 + pxx + kx) * 64 + cgc];
                        a.x += pv.x * wv1[k].x; a.y += pv.y * wv1[k].y;
                        a.z += pv.z * wv1[k].z; a.w += pv.w * wv1[k].w;
                    }
                a.x = gelu_f(a.x); a.y = gelu_f(a.y); a.z = gelu_f(a.z); a.w = gelu_f(a.w);
            }
            *(float4*)&p1[pidx * 64 + cgc] = a;
        }
    }
    __syncthreads();

    int ti = tid >> 4, tj = tid & 15;
    float wr[4][9];
#pragma unroll
    for (int s = 0; s < 4; s++)
#pragma unroll
        for (int k = 0; k < 9; k++) wr[s][k] = w2s[(4 * tj + s) * 9 + k];

#pragma unroll
    for (int r = 0; r < 4; r++) {             // conv2 + accumulate into out
        int pl = 4 * ti + r, py = pl >> 3, pxx = pl & 7;
        float cv[4] = {0.f, 0.f, 0.f, 0.f};
#pragma unroll
        for (int ky = 0; ky < 3; ky++)
#pragma unroll
            for (int kx = 0; kx < 3; kx++) {
                int k = ky * 3 + kx;
                float4 pv = *(const float4*)&p1[((py + ky) * 10 + pxx + kx) * 64 + 4 * tj];
                cv[0] += pv.x * wr[0][k];
                cv[1] += pv.y * wr[1][k];
                cv[2] += pv.z * wr[2][k];
                cv[3] += pv.w * wr[3][k];
            }
        float* op = out + (((size_t)(b * HH + y0 + py)) * WW + x0 + pxx) * 64 + 4 * tj;
        float4 o = *(const float4*)op;
        o.x += cv[0]; o.y += cv[1]; o.z += cv[2]; o.w += cv[3];
        *(float4*)op = o;
    }
}

// ---------------- launch ----------------
extern "C" void kernel_launch(void* const* d_in, const int* in_sizes, int n_in,
                              void* d_out, int out_size) {
    const float* x     = (const float*)d_in[0];
    const float* Wq    = (const float*)d_in[1];
    const float* Wk    = (const float*)d_in[2];
    const float* Wv    = (const float*)d_in[3];
    const float* resc  = (const float*)d_in[4];
    const float* Wproj = (const float*)d_in[5];
    const float* bproj = (const float*)d_in[6];
    const float* Wc1d  = (const float*)d_in[7];
    const float* bc1d  = (const float*)d_in[8];
    const float* Wpe1  = (const float*)d_in[9];
    const float* Wpe2  = (const float*)d_in[10];
    float* out = (float*)d_out;

    static cudaStream_t s_aux = [] {
        cudaStream_t s; cudaStreamCreateWithFlags(&s, cudaStreamNonBlocking); return s;
    }();
    static cudaEvent_t ev_fork = [] {
        cudaEvent_t e; cudaEventCreateWithFlags(&e, cudaEventDisableTiming); return e;
    }();
    static cudaEvent_t ev_wp = [] {
        cudaEvent_t e; cudaEventCreateWithFlags(&e, cudaEventDisableTiming); return e;
    }();

    cudaFuncSetAttribute(k23_attn, cudaFuncAttributeMaxDynamicSharedMemorySize, 16640 * 4);
    cudaFuncSetAttribute(k4a2, cudaFuncAttributeMaxDynamicSharedMemorySize, 12672 * 4);
    cudaFuncSetAttribute(k4b2, cudaFuncAttributeMaxDynamicSharedMemorySize, 16768 * 4);

    // fork: kWp on aux (no deps), attention chain on main
    cudaEventRecord(ev_fork, 0);
    cudaStreamWaitEvent(s_aux, ev_fork, 0);
    kWp<<<16, 256, 0, s_aux>>>(Wv, Wc1d);
    cudaEventRecord(ev_wp, s_aux);

    k0_zero<<<8, 1024>>>();
    k1_S<<<128, 256>>>(x);
    k23_attn<<<16, 512, 16640 * 4>>>(Wq, Wk, resc, Wproj, Wv);

    cudaStreamWaitEvent(0, ev_wp, 0);
    k4a2<<<2048, 256, 12672 * 4>>>(x, bc1d, bproj, out);
    k4b2<<<2048, 256, 16768 * 4>>>(Wpe1, Wpe2, out);
}